// round 10
// baseline (speedup 1.0000x reference)
#include <cuda_runtime.h>
#include <cuda_fp16.h>
#include <cstdint>

#define B_  4
#define S_  8192
#define D_  1024
#define H_  16
#define M_  (B_*S_)          // 32768
#define SCALE_ 0.125f
#define NSPLIT 16
#define SCHUNK (S_/NSPLIT)   // 512

// ---------------- scratch (device globals) ----------------
__device__ __half g_xh [(size_t)M_*D_];                    // x as fp16
__device__ __half g_Wqt [(size_t)D_*D_];
__device__ __half g_Wkvt[(size_t)2*D_*D_];
__device__ __half g_EQ [(size_t)M_*D_];                    // exp(Q logits)
__device__ __half g_Ykv[(size_t)M_*2*D_];                  // E=exp(K) | V (fp16)
__device__ __half g_Q  [(size_t)M_*D_];                    // normalized Q (fp16)
__device__ float g_zp[B_*H_*NSPLIT*64];
__device__ float g_Z [B_*H_*64];
__device__ float g_ctxp[(size_t)B_*H_*NSPLIT*64*64];       // 16.8 MB
__device__ float g_ctx [B_*H_*64*64];
__device__ float g_W2[(size_t)B_*D_*D_];
__device__ __half g_W2t[(size_t)B_*D_*D_];

// ---------------- helpers ----------------
__device__ __forceinline__ uint32_t smem_u32(const void* p) {
    uint32_t a;
    asm("{ .reg .u64 t; cvta.to.shared.u64 t, %1; cvt.u32.u64 %0, t; }" : "=r"(a) : "l"(p));
    return a;
}
#define SWZ(off) ((off) ^ (((off) >> 3) & 0x70))

__device__ __forceinline__ void cpa16(uint32_t s, const void* g) {
    asm volatile("cp.async.cg.shared.global [%0], [%1], 16;" :: "r"(s), "l"(g));
}
#define CP_COMMIT() asm volatile("cp.async.commit_group;" ::: "memory")
#define CP_WAITG(n) asm volatile("cp.async.wait_group %0;" :: "n"(n) : "memory")

#define LDSM4(r, addr)                                                        \
    asm volatile("ldmatrix.sync.aligned.m8n8.x4.shared.b16 {%0,%1,%2,%3}, [%4];" \
        : "=r"((r)[0]), "=r"((r)[1]), "=r"((r)[2]), "=r"((r)[3]) : "r"(addr))

#define LDSM4T(r, addr)                                                       \
    asm volatile("ldmatrix.sync.aligned.m8n8.x4.trans.shared.b16 {%0,%1,%2,%3}, [%4];" \
        : "=r"((r)[0]), "=r"((r)[1]), "=r"((r)[2]), "=r"((r)[3]) : "r"(addr))

#define MMA16816(c, a, b0, b1)                                                \
    asm volatile("mma.sync.aligned.m16n8k16.row.col.f32.f16.f16.f32 "         \
        "{%0,%1,%2,%3},{%4,%5,%6,%7},{%8,%9},{%0,%1,%2,%3};"                  \
        : "+f"((c)[0]), "+f"((c)[1]), "+f"((c)[2]), "+f"((c)[3])              \
        : "r"((a)[0]), "r"((a)[1]), "r"((a)[2]), "r"((a)[3]),                 \
          "r"(b0), "r"(b1))

static constexpr int STAGE = 32768;           // A16K B16K
static constexpr int SMEM_GEMM = 3 * STAGE;   // 96KB, 3-stage -> 2 CTAs/SM

// EPI modes: 0 = fp32 out + bias, 1 = fp16 exp(acc) all cols,
//            2 = fp16, exp(acc) only on K-columns ((n>>6)&1 == 0)
// ============================================================
// HMMA GEMM: C[M,N] = A[M,K] @ B[N,K]^T  (all fp16 operands)
// CTA 128x128xK64, 4 warps (64x64 each -> 0.25 ldsm/MMA),
// 3-stage cp.async, SW128 smem, 128 threads, 2 CTAs/SM.
// ============================================================
template<int EPI>
__global__ __launch_bounds__(128, 2) void gemm_mma(
    const uint4* __restrict__ A, const uint4* __restrict__ Bm,
    void* __restrict__ Cv, int M, int N, int K,
    size_t aBatch, size_t bBatch, size_t cBatch,
    const float* __restrict__ bias)
{
    extern __shared__ __align__(1024) char smem[];
    const uint32_t sbase = smem_u32(smem);
    const int tid = threadIdx.x, wid = tid >> 5, lane = tid & 31;
    const int bn = blockIdx.x * 128, bm = blockIdx.y * 128;
    const int z = blockIdx.z;
    A  += (size_t)z * aBatch;
    Bm += (size_t)z * bBatch;

    const int wm = (wid & 1) * 64;    // warp m-offset: 0/64
    const int wn = (wid >> 1) * 64;   // warp n-offset: 0/64
    const int Kq = K >> 3;

    const int lr = lane & 7, lq = lane >> 3;
    const uint32_t aRow = lr + (lq & 1) * 8,  aColB = (lq >> 1) * 16;
    const uint32_t bRow = lr + (lq >> 1) * 8, bColB = (lq & 1) * 16;

    float acc[4][8][4] = {};          // [mf][nf][frag]

    auto load_stage = [&](int s, int kq0) {
        uint32_t stb = sbase + s * STAGE;
#pragma unroll
        for (int ii = 0; ii < 8; ii++) {
            int i = tid + ii * 128;
            int r = i >> 3, cc = i & 7;
            uint32_t off = SWZ((uint32_t)(r * 128 + cc * 16));
            cpa16(stb + off,          A  + (size_t)(bm + r) * Kq + kq0 + cc);
            cpa16(stb + 16384 + off,  Bm + (size_t)(bn + r) * Kq + kq0 + cc);
        }
    };

    const int nch = K >> 6;
    load_stage(0, 0);  CP_COMMIT();
    load_stage(1, 8);  CP_COMMIT();

    for (int c = 0; c < nch; ++c) {
        if (c + 1 < nch) { CP_WAITG(1); } else { CP_WAITG(0); }
        __syncthreads();
        if (c + 2 < nch) { load_stage((c + 2) % 3, (c + 2) * 8); CP_COMMIT(); }

        const uint32_t stb = sbase + (c % 3) * STAGE;
#pragma unroll
        for (int t = 0; t < 4; t++) {
            uint32_t a4[4][4], b4[4][4];
#pragma unroll
            for (int mf = 0; mf < 4; mf++) {
                uint32_t off = SWZ((uint32_t)((wm + mf * 16 + aRow) * 128 + t * 32 + aColB));
                LDSM4(a4[mf], stb + off);
            }
#pragma unroll
            for (int p = 0; p < 4; p++) {
                uint32_t off = SWZ((uint32_t)((wn + p * 16 + bRow) * 128 + t * 32 + bColB));
                LDSM4(b4[p], stb + 16384 + off);
            }
#pragma unroll
            for (int mf = 0; mf < 4; mf++)
#pragma unroll
                for (int nf = 0; nf < 8; nf++) {
                    int p = nf >> 1, hh = (nf & 1) * 2;
                    MMA16816(acc[mf][nf], a4[mf], b4[p][hh], b4[p][hh + 1]);
                }
        }
    }

    // epilogue
    const int g = lane >> 2, tt = lane & 3;
#pragma unroll
    for (int mf = 0; mf < 4; mf++)
#pragma unroll
        for (int nf = 0; nf < 8; nf++) {
            int m = bm + wm + mf * 16 + g;
            int n = bn + wn + nf * 8 + tt * 2;
            float v0 = acc[mf][nf][0], v1 = acc[mf][nf][1];
            float v2 = acc[mf][nf][2], v3 = acc[mf][nf][3];
            if constexpr (EPI == 0) {
                float b0 = bias[n], b1 = bias[n + 1];
                float* C = (float*)Cv + (size_t)z * cBatch;
                *(float2*)(C + (size_t)m * N + n)       = make_float2(v0 + b0, v1 + b1);
                *(float2*)(C + (size_t)(m + 8) * N + n) = make_float2(v2 + b0, v3 + b1);
            } else {
                bool doexp = (EPI == 1) || (((n >> 6) & 1) == 0);
                if (doexp) {
                    v0 = __expf(v0); v1 = __expf(v1);
                    v2 = __expf(v2); v3 = __expf(v3);
                }
                __half* C = (__half*)Cv + (size_t)z * cBatch;
                *(__half2*)(C + (size_t)m * N + n)       = __floats2half2_rn(v0, v1);
                *(__half2*)(C + (size_t)(m + 8) * N + n) = __floats2half2_rn(v2, v3);
            }
        }
}

// ============================================================
// ctx via tensor cores:
// ctxp[bh][sp][d][e] = sum_{s in chunk} E[s,d] * V[s,e]
// ============================================================
static constexpr int CTX_STAGE = 16384;       // E 8KB + V 8KB
__global__ __launch_bounds__(128) void ctx_mma(
    const __half* __restrict__ Ykv, float* __restrict__ ctxp)
{
    __shared__ __align__(1024) char smem[2 * CTX_STAGE];
    const uint32_t sb = smem_u32(smem);
    const int bh = blockIdx.x, sp = blockIdx.y;
    const int b = bh >> 4, h = bh & 15;
    const int tid = threadIdx.x, wid = tid >> 5, lane = tid & 31;
    const __half* base = Ykv + ((size_t)(b * S_) + sp * SCHUNK) * 2048 + h * 128;

    auto load_blk = [&](int st, int s0) {
        uint32_t stb = sb + st * CTX_STAGE;
#pragma unroll
        for (int ii = 0; ii < 8; ii++) {
            int i = tid + ii * 128;
            int r = i >> 4, q = i & 15;
            const __half* g = base + (size_t)(s0 + r) * 2048 + (q & 7) * 8 + (q >> 3) * 64;
            uint32_t off = ((q < 8) ? 0u : 8192u) + SWZ((uint32_t)(r * 128 + (q & 7) * 16));
            cpa16(stb + off, g);
        }
    };

    const int wd = (wid & 1) * 32, we = (wid >> 1) * 32;
    const int lr = lane & 7, lg = lane >> 3;
    float acc[2][4][4] = {};

    load_blk(0, 0); CP_COMMIT();
    for (int blk = 0; blk < SCHUNK / 64; blk++) {
        if (blk + 1 < SCHUNK / 64) {
            load_blk((blk + 1) & 1, (blk + 1) * 64);
            CP_COMMIT(); CP_WAITG(1);
        } else {
            CP_WAITG(0);
        }
        __syncthreads();
        const uint32_t Es = sb + (blk & 1) * CTX_STAGE;
        const uint32_t Vs = Es + 8192;
#pragma unroll
        for (int t = 0; t < 4; t++) {
            uint32_t a4[2][4], b4[2][4];
#pragma unroll
            for (int mi = 0; mi < 2; mi++) {
                uint32_t srow = t * 16 + lr + ((lg >> 1) & 1) * 8;
                uint32_t scolB = (wd + mi * 16) * 2 + (lg & 1) * 16;
                LDSM4T(a4[mi], Es + SWZ(srow * 128 + scolB));
            }
#pragma unroll
            for (int np = 0; np < 2; np++) {
                uint32_t srow = t * 16 + lr + (lg & 1) * 8;
                uint32_t scolB = (we + np * 16) * 2 + (lg >> 1) * 16;
                LDSM4T(b4[np], Vs + SWZ(srow * 128 + scolB));
            }
#pragma unroll
            for (int mi = 0; mi < 2; mi++)
#pragma unroll
                for (int j = 0; j < 4; j++)
                    MMA16816(acc[mi][j], a4[mi], b4[j >> 1][(j & 1) * 2], b4[j >> 1][(j & 1) * 2 + 1]);
        }
        __syncthreads();
    }

    const int g = lane >> 2, tt = lane & 3;
    const size_t po = ((size_t)bh * NSPLIT + sp) * 4096;
#pragma unroll
    for (int mi = 0; mi < 2; mi++)
#pragma unroll
        for (int j = 0; j < 4; j++) {
            int d = wd + mi * 16 + g, e = we + j * 8 + tt * 2;
            *(float2*)(ctxp + po + (size_t)d * 64 + e)       = make_float2(acc[mi][j][0], acc[mi][j][1]);
            *(float2*)(ctxp + po + (size_t)(d + 8) * 64 + e) = make_float2(acc[mi][j][2], acc[mi][j][3]);
        }
}

// ============================================================
// Z partials: zp[bh][sp][d] = sum_{s in chunk} E[s,d]
// ============================================================
__global__ __launch_bounds__(256) void zsum(
    const __half* __restrict__ Ykv, float* __restrict__ zp)
{
    int bh = blockIdx.x, sp = blockIdx.y;
    int b = bh >> 4, h = bh & 15;
    int tid = threadIdx.x;
    int d = tid & 63, sy = tid >> 6;
    const __half* base = Ykv + ((size_t)(b * S_) + sp * SCHUNK) * 2048 + h * 128 + d;
    float z = 0.f;
    for (int s = sy; s < SCHUNK; s += 4) z += __half2float(base[(size_t)s * 2048]);
    __shared__ float sz[4][64];
    sz[sy][d] = z;
    __syncthreads();
    if (sy == 0)
        zp[((size_t)bh * NSPLIT + sp) * 64 + d] = sz[0][d] + sz[1][d] + sz[2][d] + sz[3][d];
}

__global__ void zred_kernel(const float* __restrict__ zp, float* __restrict__ Z)
{
    int bh = blockIdx.x, d = threadIdx.x;
    float s = 0.f;
#pragma unroll
    for (int i = 0; i < NSPLIT; i++) s += zp[((size_t)bh * NSPLIT + i) * 64 + d];
    Z[bh * 64 + d] = s;
}

__global__ __launch_bounds__(256) void ctx_reduce_kernel(
    const float* __restrict__ ctxp, const float* __restrict__ Z,
    float* __restrict__ ctx)
{
    int idx = blockIdx.x * 256 + threadIdx.x;
    int bh = idx >> 12, de = idx & 4095, d = de >> 6;
    float s = 0.f;
#pragma unroll
    for (int i = 0; i < NSPLIT; i++)
        s += ctxp[((size_t)bh * NSPLIT + i) * 4096 + de];
    ctx[idx] = s / Z[bh * 64 + d];
}

// ============================================================
// x fp32 -> fp16 (elementwise)
// ============================================================
__global__ __launch_bounds__(256) void x_to_h(
    const float4* __restrict__ X, __half* __restrict__ O, size_t n4)
{
    size_t i = (size_t)blockIdx.x * 256 + threadIdx.x;
    if (i >= n4) return;
    float4 v = X[i];
    __half2* p = (__half2*)(O + i * 4);
    p[0] = __floats2half2_rn(v.x, v.y);
    p[1] = __floats2half2_rn(v.z, v.w);
}

// ============================================================
// W[K,N] -> transposed fp16 [N,K]  (batched via z)
// ============================================================
__global__ __launch_bounds__(256) void transW_h(
    const float* __restrict__ W, __half* __restrict__ Th, int K, int N)
{
    __shared__ float t[32][33];
    const size_t zoff = (size_t)blockIdx.z * K * N;
    W += zoff; Th += zoff;
    int n0 = blockIdx.x * 32, k0 = blockIdx.y * 32;
    int tx = threadIdx.x & 31, ty = threadIdx.x >> 5;
#pragma unroll
    for (int i = 0; i < 32; i += 8)
        t[ty + i][tx] = W[(size_t)(k0 + ty + i) * N + n0 + tx];
    __syncthreads();
#pragma unroll
    for (int i = 0; i < 32; i += 8)
        Th[(size_t)(n0 + ty + i) * K + k0 + tx] = __float2half_rn(t[tx][ty + i]);
}

// ============================================================
// Q normalize: Q[w,:] = EQ[w,:] * SCALE / sum(EQ[w,:])
// ============================================================
__global__ __launch_bounds__(256) void qnorm(
    const __half2* __restrict__ EQ, __half2* __restrict__ Q)
{
    int w = (blockIdx.x * blockDim.x + threadIdx.x) >> 5;
    int lane = threadIdx.x & 31;
    float2 f = __half22float2(EQ[(size_t)w * 32 + lane]);
    float s = f.x + f.y;
#pragma unroll
    for (int o = 16; o; o >>= 1) s += __shfl_xor_sync(0xffffffffu, s, o);
    float inv = SCALE_ / s;
    Q[(size_t)w * 32 + lane] = __floats2half2_rn(f.x * inv, f.y * inv);
}

// ============================================================
// W2[b][h*64+d][n] = sum_e ctx[bh][d][e] * Wlin[h*64+e][n]
// ============================================================
__global__ __launch_bounds__(256) void w2_kernel(
    const float* __restrict__ ctx, const float* __restrict__ Wlin,
    float* __restrict__ W2)
{
    int bh = blockIdx.x, nb = blockIdx.y;
    int b = bh >> 4, h = bh & 15;
    __shared__ float Cs[64][64];
    __shared__ float Ws[64][64];
    int tid = threadIdx.x;
    for (int i = tid; i < 4096; i += 256)
        ((float*)Cs)[i] = ctx[(size_t)bh * 4096 + i];
    {
        int e = tid >> 2, nq = (tid & 3) << 4;
        const float* src = Wlin + (size_t)(h * 64 + e) * 1024 + nb * 64 + nq;
#pragma unroll
        for (int j = 0; j < 4; j++)
            *(float4*)&Ws[e][nq + j * 4] = *(const float4*)(src + j * 4);
    }
    __syncthreads();
    int tr = tid >> 4, tc = tid & 15;
    float acc[4][4] = {};
#pragma unroll 8
    for (int e = 0; e < 64; e++) {
        float a0 = Cs[tr*4+0][e], a1 = Cs[tr*4+1][e];
        float a2 = Cs[tr*4+2][e], a3 = Cs[tr*4+3][e];
        float4 rb = *(const float4*)&Ws[e][tc * 4];
        acc[0][0]+=a0*rb.x; acc[0][1]+=a0*rb.y; acc[0][2]+=a0*rb.z; acc[0][3]+=a0*rb.w;
        acc[1][0]+=a1*rb.x; acc[1][1]+=a1*rb.y; acc[1][2]+=a1*rb.z; acc[1][3]+=a1*rb.w;
        acc[2][0]+=a2*rb.x; acc[2][1]+=a2*rb.y; acc[2][2]+=a2*rb.z; acc[2][3]+=a2*rb.w;
        acc[3][0]+=a3*rb.x; acc[3][1]+=a3*rb.y; acc[3][2]+=a3*rb.z; acc[3][3]+=a3*rb.w;
    }
#pragma unroll
    for (int i = 0; i < 4; i++) {
        float4 o = make_float4(acc[i][0], acc[i][1], acc[i][2], acc[i][3]);
        *(float4*)(W2 + ((size_t)b * 1024 + h * 64 + tr * 4 + i) * 1024 + nb * 64 + tc * 4) = o;
    }
}

// ============================================================
extern "C" void kernel_launch(void* const* d_in, const int* in_sizes, int n_in,
                              void* d_out, int out_size)
{
    (void)in_sizes; (void)n_in; (void)out_size;
    const float* x    = (const float*)d_in[0];
    const float* Wq   = (const float*)d_in[1];
    const float* Wkv  = (const float*)d_in[2];
    const float* Wlin = (const float*)d_in[3];
    const float* blin = (const float*)d_in[4];
    float* out = (float*)d_out;

    cudaFuncSetAttribute(gemm_mma<0>, cudaFuncAttributeMaxDynamicSharedMemorySize, SMEM_GEMM);
    cudaFuncSetAttribute(gemm_mma<1>, cudaFuncAttributeMaxDynamicSharedMemorySize, SMEM_GEMM);
    cudaFuncSetAttribute(gemm_mma<2>, cudaFuncAttributeMaxDynamicSharedMemorySize, SMEM_GEMM);

    __half *pxh, *pWq, *pWkv, *pEQ, *pYkv, *pQ, *pW2t;
    float *pzp, *pZ, *pctxp, *pctx, *pW2;
    cudaGetSymbolAddress((void**)&pxh,  g_xh);
    cudaGetSymbolAddress((void**)&pWq,  g_Wqt);
    cudaGetSymbolAddress((void**)&pWkv, g_Wkvt);
    cudaGetSymbolAddress((void**)&pEQ,  g_EQ);   cudaGetSymbolAddress((void**)&pYkv, g_Ykv);
    cudaGetSymbolAddress((void**)&pQ,   g_Q);
    cudaGetSymbolAddress((void**)&pzp,  g_zp);   cudaGetSymbolAddress((void**)&pZ,   g_Z);
    cudaGetSymbolAddress((void**)&pctxp,g_ctxp); cudaGetSymbolAddress((void**)&pctx, g_ctx);
    cudaGetSymbolAddress((void**)&pW2,  g_W2);   cudaGetSymbolAddress((void**)&pW2t, g_W2t);

    dim3 blk(256);

    // 1) conversions
    x_to_h<<<(M_*D_/4)/256, blk>>>((const float4*)x, pxh, (size_t)M_*D_/4);
    transW_h<<<dim3(32, 32, 1), blk>>>(Wq,  pWq,  D_, D_);
    transW_h<<<dim3(64, 32, 1), blk>>>(Wkv, pWkv, D_, 2*D_);

    // 2) projections; exp fused in epilogue
    gemm_mma<1><<<dim3(D_/128, M_/128, 1), dim3(128), SMEM_GEMM>>>(
        (const uint4*)pxh, (const uint4*)pWq,
        pEQ, M_, D_, D_, 0, 0, 0, nullptr);
    gemm_mma<2><<<dim3(2*D_/128, M_/128, 1), dim3(128), SMEM_GEMM>>>(
        (const uint4*)pxh, (const uint4*)pWkv,
        pYkv, M_, 2*D_, D_, 0, 0, 0, nullptr);

    // 3) Q normalize
    qnorm<<<(M_*H_)/8, blk>>>((const __half2*)pEQ, (__half2*)pQ);

    // 4) ctx on tensor cores + Z column sums
    ctx_mma<<<dim3(B_*H_, NSPLIT), dim3(128)>>>(pYkv, pctxp);
    zsum<<<dim3(B_*H_, NSPLIT), blk>>>(pYkv, pzp);
    zred_kernel<<<B_*H_, 64>>>(pzp, pZ);
    ctx_reduce_kernel<<<(B_*H_*64*64)/256, blk>>>(pctxp, pZ, pctx);

    // 5) W2 = ctx @ Wlin (per head), then transpose
    w2_kernel<<<dim3(B_*H_, 16), blk>>>(pctx, Wlin, pW2);
    transW_h<<<dim3(32, 32, B_), blk>>>(pW2, pW2t, D_, D_);

    // 6) out[b] = Q[b] @ W2[b] + blin
    gemm_mma<0><<<dim3(D_/128, S_/128, B_), dim3(128), SMEM_GEMM>>>(
        (const uint4*)pQ, (const uint4*)pW2t,
        out, S_, D_, D_,
        (size_t)S_*D_/8, (size_t)D_*D_/8, (size_t)S_*D_,
        blin);
}

// round 12
// speedup vs baseline: 1.0630x; 1.0630x over previous
#include <cuda_runtime.h>
#include <cuda_fp16.h>
#include <cstdint>

#define B_  4
#define S_  8192
#define D_  1024
#define H_  16
#define M_  (B_*S_)          // 32768
#define SCALE_ 0.125f
#define NSPLIT 16
#define SCHUNK (S_/NSPLIT)   // 512

// ---------------- scratch (device globals) ----------------
__device__ __half g_xh [(size_t)M_*D_];                    // x as fp16
__device__ __half g_Wqt [(size_t)D_*D_];
__device__ __half g_Wkvt[(size_t)2*D_*D_];
__device__ __half g_Ykv[(size_t)M_*2*D_];                  // E=exp(K) | V (fp16)
__device__ __half g_Q  [(size_t)M_*D_];                    // normalized Q (fp16)
__device__ float g_Z [B_*H_*64];
__device__ float g_ctxp[(size_t)B_*H_*NSPLIT*64*64];       // 16.8 MB
__device__ float g_ctx [B_*H_*64*64];
__device__ float g_W2[(size_t)B_*D_*D_];
__device__ __half g_W2t[(size_t)B_*D_*D_];

// ---------------- helpers ----------------
__device__ __forceinline__ uint32_t smem_u32(const void* p) {
    uint32_t a;
    asm("{ .reg .u64 t; cvta.to.shared.u64 t, %1; cvt.u32.u64 %0, t; }" : "=r"(a) : "l"(p));
    return a;
}
#define SWZ(off) ((off) ^ (((off) >> 3) & 0x70))

__device__ __forceinline__ void cpa16(uint32_t s, const void* g) {
    asm volatile("cp.async.cg.shared.global [%0], [%1], 16;" :: "r"(s), "l"(g));
}
#define CP_COMMIT() asm volatile("cp.async.commit_group;" ::: "memory")
#define CP_WAITG(n) asm volatile("cp.async.wait_group %0;" :: "n"(n) : "memory")

#define LDSM4(r, addr)                                                        \
    asm volatile("ldmatrix.sync.aligned.m8n8.x4.shared.b16 {%0,%1,%2,%3}, [%4];" \
        : "=r"((r)[0]), "=r"((r)[1]), "=r"((r)[2]), "=r"((r)[3]) : "r"(addr))

#define LDSM4T(r, addr)                                                       \
    asm volatile("ldmatrix.sync.aligned.m8n8.x4.trans.shared.b16 {%0,%1,%2,%3}, [%4];" \
        : "=r"((r)[0]), "=r"((r)[1]), "=r"((r)[2]), "=r"((r)[3]) : "r"(addr))

#define MMA16816(c, a, b0, b1)                                                \
    asm volatile("mma.sync.aligned.m16n8k16.row.col.f32.f16.f16.f32 "         \
        "{%0,%1,%2,%3},{%4,%5,%6,%7},{%8,%9},{%0,%1,%2,%3};"                  \
        : "+f"((c)[0]), "+f"((c)[1]), "+f"((c)[2]), "+f"((c)[3])              \
        : "r"((a)[0]), "r"((a)[1]), "r"((a)[2]), "r"((a)[3]),                 \
          "r"(b0), "r"(b1))

static constexpr int STAGE = 32768;           // A16K B16K
static constexpr int SMEM_GEMM = 3 * STAGE;   // 96KB, 3-stage -> 2 CTAs/SM

// EPI modes:
//  0 = fp32 out + bias
//  1 = Q path: exp(acc), in-CTA per-head row softmax-normalize *SCALE, fp16 out
//  2 = KV path: exp(acc) on K-cols (n%128<64), fp16 out, + per-col Z atomics
// ============================================================
// HMMA GEMM: C[M,N] = A[M,K] @ B[N,K]^T  (all fp16 operands)
// CTA 128x128xK64, 8 warps (64x32 each), 3-stage cp.async, SW128.
// ============================================================
template<int EPI>
__global__ __launch_bounds__(256, 2) void gemm_mma(
    const uint4* __restrict__ A, const uint4* __restrict__ Bm,
    void* __restrict__ Cv, int M, int N, int K,
    size_t aBatch, size_t bBatch, size_t cBatch,
    const float* __restrict__ bias, float* __restrict__ Zg)
{
    extern __shared__ __align__(1024) char smem[];
    const uint32_t sbase = smem_u32(smem);
    const int tid = threadIdx.x, wid = tid >> 5, lane = tid & 31;
    const int bn = blockIdx.x * 128, bm = blockIdx.y * 128;
    const int z = blockIdx.z;
    A  += (size_t)z * aBatch;
    Bm += (size_t)z * bBatch;

    const int wm = (wid >> 2) * 64;
    const int wn = (wid & 3) * 32;
    const int Kq = K >> 3;

    const int lr = lane & 7, lq = lane >> 3;
    const uint32_t aRow = lr + (lq & 1) * 8,  aColB = (lq >> 1) * 16;
    const uint32_t bRow = lr + (lq >> 1) * 8, bColB = (lq & 1) * 16;

    float acc[4][4][4] = {};

    auto load_stage = [&](int s, int kq0) {
        uint32_t stb = sbase + s * STAGE;
#pragma unroll
        for (int ii = 0; ii < 4; ii++) {
            int i = tid + ii * 256;
            int r = i >> 3, cc = i & 7;
            uint32_t off = SWZ((uint32_t)(r * 128 + cc * 16));
            cpa16(stb + off,          A  + (size_t)(bm + r) * Kq + kq0 + cc);
            cpa16(stb + 16384 + off,  Bm + (size_t)(bn + r) * Kq + kq0 + cc);
        }
    };

    const int nch = K >> 6;
    load_stage(0, 0);  CP_COMMIT();
    load_stage(1, 8);  CP_COMMIT();

    for (int c = 0; c < nch; ++c) {
        if (c + 1 < nch) { CP_WAITG(1); } else { CP_WAITG(0); }
        __syncthreads();
        if (c + 2 < nch) { load_stage((c + 2) % 3, (c + 2) * 8); CP_COMMIT(); }

        const uint32_t stb = sbase + (c % 3) * STAGE;
#pragma unroll
        for (int t = 0; t < 4; t++) {
            uint32_t a4[4][4], b4[2][4];
#pragma unroll
            for (int mf = 0; mf < 4; mf++) {
                uint32_t off = SWZ((uint32_t)((wm + mf * 16 + aRow) * 128 + t * 32 + aColB));
                LDSM4(a4[mf], stb + off);
            }
#pragma unroll
            for (int p = 0; p < 2; p++) {
                uint32_t off = SWZ((uint32_t)((wn + p * 16 + bRow) * 128 + t * 32 + bColB));
                LDSM4(b4[p], stb + 16384 + off);
            }
#pragma unroll
            for (int mf = 0; mf < 4; mf++)
#pragma unroll
                for (int nf = 0; nf < 4; nf++) {
                    int p = nf >> 1, hh = (nf & 1) * 2;
                    MMA16816(acc[mf][nf], a4[mf], b4[p][hh], b4[p][hh + 1]);
                }
        }
    }

    // ---------------- epilogue ----------------
    const int g = lane >> 2, tt = lane & 3;

    if constexpr (EPI == 0) {
#pragma unroll
        for (int mf = 0; mf < 4; mf++)
#pragma unroll
            for (int nf = 0; nf < 4; nf++) {
                int m = bm + wm + mf * 16 + g;
                int n = bn + wn + nf * 8 + tt * 2;
                float b0 = bias[n], b1 = bias[n + 1];
                float* C = (float*)Cv + (size_t)z * cBatch;
                *(float2*)(C + (size_t)m * N + n) =
                    make_float2(acc[mf][nf][0] + b0, acc[mf][nf][1] + b1);
                *(float2*)(C + (size_t)(m + 8) * N + n) =
                    make_float2(acc[mf][nf][2] + b0, acc[mf][nf][3] + b1);
            }
    }

    if constexpr (EPI == 1) {
        // exp in fp32
#pragma unroll
        for (int mf = 0; mf < 4; mf++)
#pragma unroll
            for (int nf = 0; nf < 4; nf++)
#pragma unroll
                for (int q = 0; q < 4; q++)
                    acc[mf][nf][q] = __expf(acc[mf][nf][q]);
        // per-head row sums: CTA n-tile = 2 heads; warp wholly in one head
        __syncthreads();                          // stage smem now reusable
        float* sums = (float*)smem;               // [128 rows][2 hcols]
        sums[tid] = 0.f;                          // 256 slots exactly
        __syncthreads();
        const int hcol = (wn >= 64) ? 1 : 0;
#pragma unroll
        for (int mf = 0; mf < 4; mf++) {
            float sA = 0.f, sB = 0.f;
#pragma unroll
            for (int nf = 0; nf < 4; nf++) {
                sA += acc[mf][nf][0] + acc[mf][nf][1];
                sB += acc[mf][nf][2] + acc[mf][nf][3];
            }
            // quad reduce over tt (lanes 4g..4g+3 share rows)
            sA += __shfl_xor_sync(0xffffffffu, sA, 1);
            sA += __shfl_xor_sync(0xffffffffu, sA, 2);
            sB += __shfl_xor_sync(0xffffffffu, sB, 1);
            sB += __shfl_xor_sync(0xffffffffu, sB, 2);
            if (tt == 0) {
                atomicAdd(&sums[(wm + mf * 16 + g) * 2 + hcol], sA);
                atomicAdd(&sums[(wm + mf * 16 + g + 8) * 2 + hcol], sB);
            }
        }
        __syncthreads();
#pragma unroll
        for (int mf = 0; mf < 4; mf++) {
            float invA = SCALE_ / sums[(wm + mf * 16 + g) * 2 + hcol];
            float invB = SCALE_ / sums[(wm + mf * 16 + g + 8) * 2 + hcol];
#pragma unroll
            for (int nf = 0; nf < 4; nf++) {
                int m = bm + wm + mf * 16 + g;
                int n = bn + wn + nf * 8 + tt * 2;
                __half* C = (__half*)Cv;
                *(__half2*)(C + (size_t)m * N + n) =
                    __floats2half2_rn(acc[mf][nf][0] * invA, acc[mf][nf][1] * invA);
                *(__half2*)(C + (size_t)(m + 8) * N + n) =
                    __floats2half2_rn(acc[mf][nf][2] * invB, acc[mf][nf][3] * invB);
            }
        }
    }

    if constexpr (EPI == 2) {
        const bool kcols = (wn < 64);             // n%128<64 -> K half of head
#pragma unroll
        for (int mf = 0; mf < 4; mf++)
#pragma unroll
            for (int nf = 0; nf < 4; nf++) {
                int m = bm + wm + mf * 16 + g;
                int n = bn + wn + nf * 8 + tt * 2;
                float v0 = acc[mf][nf][0], v1 = acc[mf][nf][1];
                float v2 = acc[mf][nf][2], v3 = acc[mf][nf][3];
                if (kcols) {
                    v0 = __expf(v0); v1 = __expf(v1);
                    v2 = __expf(v2); v3 = __expf(v3);
                    acc[mf][nf][0] = v0; acc[mf][nf][1] = v1;
                    acc[mf][nf][2] = v2; acc[mf][nf][3] = v3;
                }
                __half* C = (__half*)Cv;
                *(__half2*)(C + (size_t)m * N + n)       = __floats2half2_rn(v0, v1);
                *(__half2*)(C + (size_t)(m + 8) * N + n) = __floats2half2_rn(v2, v3);
            }
        // per-CTA column sums of E -> global Z (CTA rows all in one b, one head)
        __syncthreads();                          // stage smem reusable
        float* zs = (float*)smem;                 // [64] K-cols of this head
        if (tid < 64) zs[tid] = 0.f;
        __syncthreads();
        if (kcols) {
#pragma unroll
            for (int nf = 0; nf < 4; nf++) {
                float c0 = 0.f, c1 = 0.f;
#pragma unroll
                for (int mf = 0; mf < 4; mf++) {
                    c0 += acc[mf][nf][0] + acc[mf][nf][2];
                    c1 += acc[mf][nf][1] + acc[mf][nf][3];
                }
                int col = wn + nf * 8 + tt * 2;   // 0..63
                atomicAdd(&zs[col], c0);
                atomicAdd(&zs[col + 1], c1);
            }
        }
        __syncthreads();
        if (tid < 64) {
            int b = bm >> 13;                     // bm / 8192
            int h = bn >> 7;                      // bn / 128
            atomicAdd(&Zg[(b * 16 + h) * 64 + tid], zs[tid]);
        }
    }
}

// ============================================================
// zero Z
// ============================================================
__global__ void zeroZ(float* __restrict__ Z)
{
    Z[blockIdx.x * 256 + threadIdx.x] = 0.f;
}

// ============================================================
// ctx via tensor cores:
// ctxp[bh][sp][d][e] = sum_{s in chunk} E[s,d] * V[s,e]
// ============================================================
static constexpr int CTX_STAGE = 16384;       // E 8KB + V 8KB
__global__ __launch_bounds__(128) void ctx_mma(
    const __half* __restrict__ Ykv, float* __restrict__ ctxp)
{
    __shared__ __align__(1024) char smem[2 * CTX_STAGE];
    const uint32_t sb = smem_u32(smem);
    const int bh = blockIdx.x, sp = blockIdx.y;
    const int b = bh >> 4, h = bh & 15;
    const int tid = threadIdx.x, wid = tid >> 5, lane = tid & 31;
    const __half* base = Ykv + ((size_t)(b * S_) + sp * SCHUNK) * 2048 + h * 128;

    auto load_blk = [&](int st, int s0) {
        uint32_t stb = sb + st * CTX_STAGE;
#pragma unroll
        for (int ii = 0; ii < 8; ii++) {
            int i = tid + ii * 128;
            int r = i >> 4, q = i & 15;
            const __half* g = base + (size_t)(s0 + r) * 2048 + (q & 7) * 8 + (q >> 3) * 64;
            uint32_t off = ((q < 8) ? 0u : 8192u) + SWZ((uint32_t)(r * 128 + (q & 7) * 16));
            cpa16(stb + off, g);
        }
    };

    const int wd = (wid & 1) * 32, we = (wid >> 1) * 32;
    const int lr = lane & 7, lg = lane >> 3;
    float acc[2][4][4] = {};

    load_blk(0, 0); CP_COMMIT();
    for (int blk = 0; blk < SCHUNK / 64; blk++) {
        if (blk + 1 < SCHUNK / 64) {
            load_blk((blk + 1) & 1, (blk + 1) * 64);
            CP_COMMIT(); CP_WAITG(1);
        } else {
            CP_WAITG(0);
        }
        __syncthreads();
        const uint32_t Es = sb + (blk & 1) * CTX_STAGE;
        const uint32_t Vs = Es + 8192;
#pragma unroll
        for (int t = 0; t < 4; t++) {
            uint32_t a4[2][4], b4[2][4];
#pragma unroll
            for (int mi = 0; mi < 2; mi++) {
                uint32_t srow = t * 16 + lr + ((lg >> 1) & 1) * 8;
                uint32_t scolB = (wd + mi * 16) * 2 + (lg & 1) * 16;
                LDSM4T(a4[mi], Es + SWZ(srow * 128 + scolB));
            }
#pragma unroll
            for (int np = 0; np < 2; np++) {
                uint32_t srow = t * 16 + lr + (lg & 1) * 8;
                uint32_t scolB = (we + np * 16) * 2 + (lg >> 1) * 16;
                LDSM4T(b4[np], Vs + SWZ(srow * 128 + scolB));
            }
#pragma unroll
            for (int mi = 0; mi < 2; mi++)
#pragma unroll
                for (int j = 0; j < 4; j++)
                    MMA16816(acc[mi][j], a4[mi], b4[j >> 1][(j & 1) * 2], b4[j >> 1][(j & 1) * 2 + 1]);
        }
        __syncthreads();
    }

    const int g = lane >> 2, tt = lane & 3;
    const size_t po = ((size_t)bh * NSPLIT + sp) * 4096;
#pragma unroll
    for (int mi = 0; mi < 2; mi++)
#pragma unroll
        for (int j = 0; j < 4; j++) {
            int d = wd + mi * 16 + g, e = we + j * 8 + tt * 2;
            *(float2*)(ctxp + po + (size_t)d * 64 + e)       = make_float2(acc[mi][j][0], acc[mi][j][1]);
            *(float2*)(ctxp + po + (size_t)(d + 8) * 64 + e) = make_float2(acc[mi][j][2], acc[mi][j][3]);
        }
}

__global__ __launch_bounds__(256) void ctx_reduce_kernel(
    const float* __restrict__ ctxp, const float* __restrict__ Z,
    float* __restrict__ ctx)
{
    int idx = blockIdx.x * 256 + threadIdx.x;
    int bh = idx >> 12, de = idx & 4095, d = de >> 6;
    float s = 0.f;
#pragma unroll
    for (int i = 0; i < NSPLIT; i++)
        s += ctxp[((size_t)bh * NSPLIT + i) * 4096 + de];
    ctx[idx] = s / Z[bh * 64 + d];
}

// ============================================================
// x fp32 -> fp16 (elementwise)
// ============================================================
__global__ __launch_bounds__(256) void x_to_h(
    const float4* __restrict__ X, __half* __restrict__ O, size_t n4)
{
    size_t i = (size_t)blockIdx.x * 256 + threadIdx.x;
    if (i >= n4) return;
    float4 v = X[i];
    __half2* p = (__half2*)(O + i * 4);
    p[0] = __floats2half2_rn(v.x, v.y);
    p[1] = __floats2half2_rn(v.z, v.w);
}

// ============================================================
// W[K,N] -> transposed fp16 [N,K]  (batched via z)
// ============================================================
__global__ __launch_bounds__(256) void transW_h(
    const float* __restrict__ W, __half* __restrict__ Th, int K, int N)
{
    __shared__ float t[32][33];
    const size_t zoff = (size_t)blockIdx.z * K * N;
    W += zoff; Th += zoff;
    int n0 = blockIdx.x * 32, k0 = blockIdx.y * 32;
    int tx = threadIdx.x & 31, ty = threadIdx.x >> 5;
#pragma unroll
    for (int i = 0; i < 32; i += 8)
        t[ty + i][tx] = W[(size_t)(k0 + ty + i) * N + n0 + tx];
    __syncthreads();
#pragma unroll
    for (int i = 0; i < 32; i += 8)
        Th[(size_t)(n0 + ty + i) * K + k0 + tx] = __float2half_rn(t[tx][ty + i]);
}

// ============================================================
// W2[b][h*64+d][n] = sum_e ctx[bh][d][e] * Wlin[h*64+e][n]
// ============================================================
__global__ __launch_bounds__(256) void w2_kernel(
    const float* __restrict__ ctx, const float* __restrict__ Wlin,
    float* __restrict__ W2)
{
    int bh = blockIdx.x, nb = blockIdx.y;
    int b = bh >> 4, h = bh & 15;
    __shared__ float Cs[64][64];
    __shared__ float Ws[64][64];
    int tid = threadIdx.x;
    for (int i = tid; i < 4096; i += 256)
        ((float*)Cs)[i] = ctx[(size_t)bh * 4096 + i];
    {
        int e = tid >> 2, nq = (tid & 3) << 4;
        const float* src = Wlin + (size_t)(h * 64 + e) * 1024 + nb * 64 + nq;
#pragma unroll
        for (int j = 0; j < 4; j++)
            *(float4*)&Ws[e][nq + j * 4] = *(const float4*)(src + j * 4);
    }
    __syncthreads();
    int tr = tid >> 4, tc = tid & 15;
    float acc[4][4] = {};
#pragma unroll 8
    for (int e = 0; e < 64; e++) {
        float a0 = Cs[tr*4+0][e], a1 = Cs[tr*4+1][e];
        float a2 = Cs[tr*4+2][e], a3 = Cs[tr*4+3][e];
        float4 rb = *(const float4*)&Ws[e][tc * 4];
        acc[0][0]+=a0*rb.x; acc[0][1]+=a0*rb.y; acc[0][2]+=a0*rb.z; acc[0][3]+=a0*rb.w;
        acc[1][0]+=a1*rb.x; acc[1][1]+=a1*rb.y; acc[1][2]+=a1*rb.z; acc[1][3]+=a1*rb.w;
        acc[2][0]+=a2*rb.x; acc[2][1]+=a2*rb.y; acc[2][2]+=a2*rb.z; acc[2][3]+=a2*rb.w;
        acc[3][0]+=a3*rb.x; acc[3][1]+=a3*rb.y; acc[3][2]+=a3*rb.z; acc[3][3]+=a3*rb.w;
    }
#pragma unroll
    for (int i = 0; i < 4; i++) {
        float4 o = make_float4(acc[i][0], acc[i][1], acc[i][2], acc[i][3]);
        *(float4*)(W2 + ((size_t)b * 1024 + h * 64 + tr * 4 + i) * 1024 + nb * 64 + tc * 4) = o;
    }
}

// ============================================================
extern "C" void kernel_launch(void* const* d_in, const int* in_sizes, int n_in,
                              void* d_out, int out_size)
{
    (void)in_sizes; (void)n_in; (void)out_size;
    const float* x    = (const float*)d_in[0];
    const float* Wq   = (const float*)d_in[1];
    const float* Wkv  = (const float*)d_in[2];
    const float* Wlin = (const float*)d_in[3];
    const float* blin = (const float*)d_in[4];
    float* out = (float*)d_out;

    cudaFuncSetAttribute(gemm_mma<0>, cudaFuncAttributeMaxDynamicSharedMemorySize, SMEM_GEMM);
    cudaFuncSetAttribute(gemm_mma<1>, cudaFuncAttributeMaxDynamicSharedMemorySize, SMEM_GEMM);
    cudaFuncSetAttribute(gemm_mma<2>, cudaFuncAttributeMaxDynamicSharedMemorySize, SMEM_GEMM);

    __half *pxh, *pWq, *pWkv, *pYkv, *pQ, *pW2t;
    float *pZ, *pctxp, *pctx, *pW2;
    cudaGetSymbolAddress((void**)&pxh,  g_xh);
    cudaGetSymbolAddress((void**)&pWq,  g_Wqt);
    cudaGetSymbolAddress((void**)&pWkv, g_Wkvt);
    cudaGetSymbolAddress((void**)&pYkv, g_Ykv);
    cudaGetSymbolAddress((void**)&pQ,   g_Q);
    cudaGetSymbolAddress((void**)&pZ,   g_Z);
    cudaGetSymbolAddress((void**)&pctxp,g_ctxp); cudaGetSymbolAddress((void**)&pctx, g_ctx);
    cudaGetSymbolAddress((void**)&pW2,  g_W2);   cudaGetSymbolAddress((void**)&pW2t, g_W2t);

    dim3 blk(256);

    // 1) conversions + Z zero
    x_to_h<<<(M_*D_/4)/256, blk>>>((const float4*)x, pxh, (size_t)M_*D_/4);
    transW_h<<<dim3(32, 32, 1), blk>>>(Wq,  pWq,  D_, D_);
    transW_h<<<dim3(64, 32, 1), blk>>>(Wkv, pWkv, D_, 2*D_);
    zeroZ<<<16, 256>>>(pZ);

    // 2) Q-proj with fused softmax (writes normalized Q directly)
    gemm_mma<1><<<dim3(D_/128, M_/128, 1), blk, SMEM_GEMM>>>(
        (const uint4*)pxh, (const uint4*)pWq,
        pQ, M_, D_, D_, 0, 0, 0, nullptr, nullptr);
    // 3) KV-proj with fused exp(K) + Z column-sum atomics
    gemm_mma<2><<<dim3(2*D_/128, M_/128, 1), blk, SMEM_GEMM>>>(
        (const uint4*)pxh, (const uint4*)pWkv,
        pYkv, M_, 2*D_, D_, 0, 0, 0, nullptr, pZ);

    // 4) ctx on tensor cores, reduce with 1/Z
    ctx_mma<<<dim3(B_*H_, NSPLIT), dim3(128)>>>(pYkv, pctxp);
    ctx_reduce_kernel<<<(B_*H_*64*64)/256, blk>>>(pctxp, pZ, pctx);

    // 5) W2 = ctx @ Wlin (per head), then transpose
    w2_kernel<<<dim3(B_*H_, 16), blk>>>(pctx, Wlin, pW2);
    transW_h<<<dim3(32, 32, B_), blk>>>(pW2, pW2t, D_, D_);

    // 6) out[b] = Q[b] @ W2[b] + blin
    gemm_mma<0><<<dim3(D_/128, S_/128, B_), blk, SMEM_GEMM>>>(
        (const uint4*)pQ, (const uint4*)pW2t,
        out, S_, D_, D_,
        (size_t)S_*D_/8, (size_t)D_*D_/8, (size_t)S_*D_,
        blin, nullptr);
}

// round 13
// speedup vs baseline: 1.0790x; 1.0151x over previous
#include <cuda_runtime.h>
#include <cuda_fp16.h>
#include <cstdint>

#define B_  4
#define S_  8192
#define D_  1024
#define H_  16
#define M_  (B_*S_)          // 32768
#define SCALE_ 0.125f
#define NSPLIT 16
#define SCHUNK (S_/NSPLIT)   // 512

// ---------------- scratch (device globals) ----------------
__device__ __half g_xh [(size_t)M_*D_];                    // x as fp16
__device__ __half g_Wqt [(size_t)D_*D_];
__device__ __half g_Wkvt[(size_t)2*D_*D_];
__device__ __half g_Ykv[(size_t)M_*2*D_];                  // E=exp(K) | V (fp16)
__device__ __half g_Q  [(size_t)M_*D_];                    // normalized Q (fp16)
__device__ float g_Z [B_*H_*64];
__device__ float g_ctxp[(size_t)B_*H_*NSPLIT*64*64];       // 16.8 MB
__device__ float g_ctx [B_*H_*64*64];
__device__ float g_W2[(size_t)B_*D_*D_];
__device__ __half g_W2t[(size_t)B_*D_*D_];

// ---------------- fork/join resources (static init; no device mem) ----
static cudaStream_t g_s2;
static cudaEvent_t  g_eX, g_eJ;
namespace {
struct _StreamInit {
    _StreamInit() {
        cudaStreamCreateWithFlags(&g_s2, cudaStreamNonBlocking);
        cudaEventCreateWithFlags(&g_eX, cudaEventDisableTiming);
        cudaEventCreateWithFlags(&g_eJ, cudaEventDisableTiming);
    }
} _streamInit;
}

// ---------------- helpers ----------------
__device__ __forceinline__ uint32_t smem_u32(const void* p) {
    uint32_t a;
    asm("{ .reg .u64 t; cvta.to.shared.u64 t, %1; cvt.u32.u64 %0, t; }" : "=r"(a) : "l"(p));
    return a;
}
#define SWZ(off) ((off) ^ (((off) >> 3) & 0x70))

__device__ __forceinline__ void cpa16(uint32_t s, const void* g) {
    asm volatile("cp.async.cg.shared.global [%0], [%1], 16;" :: "r"(s), "l"(g));
}
#define CP_COMMIT() asm volatile("cp.async.commit_group;" ::: "memory")
#define CP_WAITG(n) asm volatile("cp.async.wait_group %0;" :: "n"(n) : "memory")

#define LDSM4(r, addr)                                                        \
    asm volatile("ldmatrix.sync.aligned.m8n8.x4.shared.b16 {%0,%1,%2,%3}, [%4];" \
        : "=r"((r)[0]), "=r"((r)[1]), "=r"((r)[2]), "=r"((r)[3]) : "r"(addr))

#define LDSM4T(r, addr)                                                       \
    asm volatile("ldmatrix.sync.aligned.m8n8.x4.trans.shared.b16 {%0,%1,%2,%3}, [%4];" \
        : "=r"((r)[0]), "=r"((r)[1]), "=r"((r)[2]), "=r"((r)[3]) : "r"(addr))

#define MMA16816(c, a, b0, b1)                                                \
    asm volatile("mma.sync.aligned.m16n8k16.row.col.f32.f16.f16.f32 "         \
        "{%0,%1,%2,%3},{%4,%5,%6,%7},{%8,%9},{%0,%1,%2,%3};"                  \
        : "+f"((c)[0]), "+f"((c)[1]), "+f"((c)[2]), "+f"((c)[3])              \
        : "r"((a)[0]), "r"((a)[1]), "r"((a)[2]), "r"((a)[3]),                 \
          "r"(b0), "r"(b1))

static constexpr int STAGE = 32768;           // A16K B16K
static constexpr int SMEM_GEMM = 3 * STAGE;   // 96KB, 3-stage -> 2 CTAs/SM

// EPI modes:
//  0 = fp32 out + bias
//  1 = Q path: exp(acc), in-CTA per-head row softmax-normalize *SCALE, fp16 out
//  2 = KV path: exp(acc) on K-cols (n%128<64), fp16 out, + per-col Z atomics
// ============================================================
// HMMA GEMM: C[M,N] = A[M,K] @ B[N,K]^T  (all fp16 operands)
// CTA 128x128xK64, 8 warps (64x32 each), 3-stage cp.async, SW128.
// ============================================================
template<int EPI>
__global__ __launch_bounds__(256, 2) void gemm_mma(
    const uint4* __restrict__ A, const uint4* __restrict__ Bm,
    void* __restrict__ Cv, int M, int N, int K,
    size_t aBatch, size_t bBatch, size_t cBatch,
    const float* __restrict__ bias, float* __restrict__ Zg)
{
    extern __shared__ __align__(1024) char smem[];
    const uint32_t sbase = smem_u32(smem);
    const int tid = threadIdx.x, wid = tid >> 5, lane = tid & 31;
    const int bn = blockIdx.x * 128, bm = blockIdx.y * 128;
    const int z = blockIdx.z;
    A  += (size_t)z * aBatch;
    Bm += (size_t)z * bBatch;

    const int wm = (wid >> 2) * 64;
    const int wn = (wid & 3) * 32;
    const int Kq = K >> 3;

    const int lr = lane & 7, lq = lane >> 3;
    const uint32_t aRow = lr + (lq & 1) * 8,  aColB = (lq >> 1) * 16;
    const uint32_t bRow = lr + (lq >> 1) * 8, bColB = (lq & 1) * 16;

    float acc[4][4][4] = {};

    auto load_stage = [&](int s, int kq0) {
        uint32_t stb = sbase + s * STAGE;
#pragma unroll
        for (int ii = 0; ii < 4; ii++) {
            int i = tid + ii * 256;
            int r = i >> 3, cc = i & 7;
            uint32_t off = SWZ((uint32_t)(r * 128 + cc * 16));
            cpa16(stb + off,          A  + (size_t)(bm + r) * Kq + kq0 + cc);
            cpa16(stb + 16384 + off,  Bm + (size_t)(bn + r) * Kq + kq0 + cc);
        }
    };

    const int nch = K >> 6;
    load_stage(0, 0);  CP_COMMIT();
    load_stage(1, 8);  CP_COMMIT();

    for (int c = 0; c < nch; ++c) {
        if (c + 1 < nch) { CP_WAITG(1); } else { CP_WAITG(0); }
        __syncthreads();
        if (c + 2 < nch) { load_stage((c + 2) % 3, (c + 2) * 8); CP_COMMIT(); }

        const uint32_t stb = sbase + (c % 3) * STAGE;
#pragma unroll
        for (int t = 0; t < 4; t++) {
            uint32_t a4[4][4], b4[2][4];
#pragma unroll
            for (int mf = 0; mf < 4; mf++) {
                uint32_t off = SWZ((uint32_t)((wm + mf * 16 + aRow) * 128 + t * 32 + aColB));
                LDSM4(a4[mf], stb + off);
            }
#pragma unroll
            for (int p = 0; p < 2; p++) {
                uint32_t off = SWZ((uint32_t)((wn + p * 16 + bRow) * 128 + t * 32 + bColB));
                LDSM4(b4[p], stb + 16384 + off);
            }
#pragma unroll
            for (int mf = 0; mf < 4; mf++)
#pragma unroll
                for (int nf = 0; nf < 4; nf++) {
                    int p = nf >> 1, hh = (nf & 1) * 2;
                    MMA16816(acc[mf][nf], a4[mf], b4[p][hh], b4[p][hh + 1]);
                }
        }
    }

    // ---------------- epilogue ----------------
    const int g = lane >> 2, tt = lane & 3;

    if constexpr (EPI == 0) {
#pragma unroll
        for (int mf = 0; mf < 4; mf++)
#pragma unroll
            for (int nf = 0; nf < 4; nf++) {
                int m = bm + wm + mf * 16 + g;
                int n = bn + wn + nf * 8 + tt * 2;
                float b0 = bias[n], b1 = bias[n + 1];
                float* C = (float*)Cv + (size_t)z * cBatch;
                *(float2*)(C + (size_t)m * N + n) =
                    make_float2(acc[mf][nf][0] + b0, acc[mf][nf][1] + b1);
                *(float2*)(C + (size_t)(m + 8) * N + n) =
                    make_float2(acc[mf][nf][2] + b0, acc[mf][nf][3] + b1);
            }
    }

    if constexpr (EPI == 1) {
#pragma unroll
        for (int mf = 0; mf < 4; mf++)
#pragma unroll
            for (int nf = 0; nf < 4; nf++)
#pragma unroll
                for (int q = 0; q < 4; q++)
                    acc[mf][nf][q] = __expf(acc[mf][nf][q]);
        __syncthreads();                          // stage smem now reusable
        float* sums = (float*)smem;               // [128 rows][2 hcols]
        sums[tid] = 0.f;
        __syncthreads();
        const int hcol = (wn >= 64) ? 1 : 0;
#pragma unroll
        for (int mf = 0; mf < 4; mf++) {
            float sA = 0.f, sB = 0.f;
#pragma unroll
            for (int nf = 0; nf < 4; nf++) {
                sA += acc[mf][nf][0] + acc[mf][nf][1];
                sB += acc[mf][nf][2] + acc[mf][nf][3];
            }
            sA += __shfl_xor_sync(0xffffffffu, sA, 1);
            sA += __shfl_xor_sync(0xffffffffu, sA, 2);
            sB += __shfl_xor_sync(0xffffffffu, sB, 1);
            sB += __shfl_xor_sync(0xffffffffu, sB, 2);
            if (tt == 0) {
                atomicAdd(&sums[(wm + mf * 16 + g) * 2 + hcol], sA);
                atomicAdd(&sums[(wm + mf * 16 + g + 8) * 2 + hcol], sB);
            }
        }
        __syncthreads();
#pragma unroll
        for (int mf = 0; mf < 4; mf++) {
            float invA = SCALE_ / sums[(wm + mf * 16 + g) * 2 + hcol];
            float invB = SCALE_ / sums[(wm + mf * 16 + g + 8) * 2 + hcol];
#pragma unroll
            for (int nf = 0; nf < 4; nf++) {
                int m = bm + wm + mf * 16 + g;
                int n = bn + wn + nf * 8 + tt * 2;
                __half* C = (__half*)Cv;
                *(__half2*)(C + (size_t)m * N + n) =
                    __floats2half2_rn(acc[mf][nf][0] * invA, acc[mf][nf][1] * invA);
                *(__half2*)(C + (size_t)(m + 8) * N + n) =
                    __floats2half2_rn(acc[mf][nf][2] * invB, acc[mf][nf][3] * invB);
            }
        }
    }

    if constexpr (EPI == 2) {
        const bool kcols = (wn < 64);             // n%128<64 -> K half of head
#pragma unroll
        for (int mf = 0; mf < 4; mf++)
#pragma unroll
            for (int nf = 0; nf < 4; nf++) {
                int m = bm + wm + mf * 16 + g;
                int n = bn + wn + nf * 8 + tt * 2;
                float v0 = acc[mf][nf][0], v1 = acc[mf][nf][1];
                float v2 = acc[mf][nf][2], v3 = acc[mf][nf][3];
                if (kcols) {
                    v0 = __expf(v0); v1 = __expf(v1);
                    v2 = __expf(v2); v3 = __expf(v3);
                    acc[mf][nf][0] = v0; acc[mf][nf][1] = v1;
                    acc[mf][nf][2] = v2; acc[mf][nf][3] = v3;
                }
                __half* C = (__half*)Cv;
                *(__half2*)(C + (size_t)m * N + n)       = __floats2half2_rn(v0, v1);
                *(__half2*)(C + (size_t)(m + 8) * N + n) = __floats2half2_rn(v2, v3);
            }
        __syncthreads();
        float* zs = (float*)smem;                 // [64] K-cols of this head
        if (tid < 64) zs[tid] = 0.f;
        __syncthreads();
        if (kcols) {
#pragma unroll
            for (int nf = 0; nf < 4; nf++) {
                float c0 = 0.f, c1 = 0.f;
#pragma unroll
                for (int mf = 0; mf < 4; mf++) {
                    c0 += acc[mf][nf][0] + acc[mf][nf][2];
                    c1 += acc[mf][nf][1] + acc[mf][nf][3];
                }
                int col = wn + nf * 8 + tt * 2;
                atomicAdd(&zs[col], c0);
                atomicAdd(&zs[col + 1], c1);
            }
        }
        __syncthreads();
        if (tid < 64) {
            int b = bm >> 13;
            int h = bn >> 7;
            atomicAdd(&Zg[(b * 16 + h) * 64 + tid], zs[tid]);
        }
    }
}

// ============================================================
// zero Z
// ============================================================
__global__ void zeroZ(float* __restrict__ Z)
{
    Z[blockIdx.x * 256 + threadIdx.x] = 0.f;
}

// ============================================================
// ctx via tensor cores:
// ctxp[bh][sp][d][e] = sum_{s in chunk} E[s,d] * V[s,e]
// ============================================================
static constexpr int CTX_STAGE = 16384;       // E 8KB + V 8KB
__global__ __launch_bounds__(128) void ctx_mma(
    const __half* __restrict__ Ykv, float* __restrict__ ctxp)
{
    __shared__ __align__(1024) char smem[2 * CTX_STAGE];
    const uint32_t sb = smem_u32(smem);
    const int bh = blockIdx.x, sp = blockIdx.y;
    const int b = bh >> 4, h = bh & 15;
    const int tid = threadIdx.x, wid = tid >> 5, lane = tid & 31;
    const __half* base = Ykv + ((size_t)(b * S_) + sp * SCHUNK) * 2048 + h * 128;

    auto load_blk = [&](int st, int s0) {
        uint32_t stb = sb + st * CTX_STAGE;
#pragma unroll
        for (int ii = 0; ii < 8; ii++) {
            int i = tid + ii * 128;
            int r = i >> 4, q = i & 15;
            const __half* g = base + (size_t)(s0 + r) * 2048 + (q & 7) * 8 + (q >> 3) * 64;
            uint32_t off = ((q < 8) ? 0u : 8192u) + SWZ((uint32_t)(r * 128 + (q & 7) * 16));
            cpa16(stb + off, g);
        }
    };

    const int wd = (wid & 1) * 32, we = (wid >> 1) * 32;
    const int lr = lane & 7, lg = lane >> 3;
    float acc[2][4][4] = {};

    load_blk(0, 0); CP_COMMIT();
    for (int blk = 0; blk < SCHUNK / 64; blk++) {
        if (blk + 1 < SCHUNK / 64) {
            load_blk((blk + 1) & 1, (blk + 1) * 64);
            CP_COMMIT(); CP_WAITG(1);
        } else {
            CP_WAITG(0);
        }
        __syncthreads();
        const uint32_t Es = sb + (blk & 1) * CTX_STAGE;
        const uint32_t Vs = Es + 8192;
#pragma unroll
        for (int t = 0; t < 4; t++) {
            uint32_t a4[2][4], b4[2][4];
#pragma unroll
            for (int mi = 0; mi < 2; mi++) {
                uint32_t srow = t * 16 + lr + ((lg >> 1) & 1) * 8;
                uint32_t scolB = (wd + mi * 16) * 2 + (lg & 1) * 16;
                LDSM4T(a4[mi], Es + SWZ(srow * 128 + scolB));
            }
#pragma unroll
            for (int np = 0; np < 2; np++) {
                uint32_t srow = t * 16 + lr + (lg & 1) * 8;
                uint32_t scolB = (we + np * 16) * 2 + (lg >> 1) * 16;
                LDSM4T(b4[np], Vs + SWZ(srow * 128 + scolB));
            }
#pragma unroll
            for (int mi = 0; mi < 2; mi++)
#pragma unroll
                for (int j = 0; j < 4; j++)
                    MMA16816(acc[mi][j], a4[mi], b4[j >> 1][(j & 1) * 2], b4[j >> 1][(j & 1) * 2 + 1]);
        }
        __syncthreads();
    }

    const int g = lane >> 2, tt = lane & 3;
    const size_t po = ((size_t)bh * NSPLIT + sp) * 4096;
#pragma unroll
    for (int mi = 0; mi < 2; mi++)
#pragma unroll
        for (int j = 0; j < 4; j++) {
            int d = wd + mi * 16 + g, e = we + j * 8 + tt * 2;
            *(float2*)(ctxp + po + (size_t)d * 64 + e)       = make_float2(acc[mi][j][0], acc[mi][j][1]);
            *(float2*)(ctxp + po + (size_t)(d + 8) * 64 + e) = make_float2(acc[mi][j][2], acc[mi][j][3]);
        }
}

__global__ __launch_bounds__(256) void ctx_reduce_kernel(
    const float* __restrict__ ctxp, const float* __restrict__ Z,
    float* __restrict__ ctx)
{
    int idx = blockIdx.x * 256 + threadIdx.x;
    int bh = idx >> 12, de = idx & 4095, d = de >> 6;
    float s = 0.f;
#pragma unroll
    for (int i = 0; i < NSPLIT; i++)
        s += ctxp[((size_t)bh * NSPLIT + i) * 4096 + de];
    ctx[idx] = s / Z[bh * 64 + d];
}

// ============================================================
// x fp32 -> fp16 (elementwise)
// ============================================================
__global__ __launch_bounds__(256) void x_to_h(
    const float4* __restrict__ X, __half* __restrict__ O, size_t n4)
{
    size_t i = (size_t)blockIdx.x * 256 + threadIdx.x;
    if (i >= n4) return;
    float4 v = X[i];
    __half2* p = (__half2*)(O + i * 4);
    p[0] = __floats2half2_rn(v.x, v.y);
    p[1] = __floats2half2_rn(v.z, v.w);
}

// ============================================================
// W[K,N] -> transposed fp16 [N,K]  (batched via z)
// ============================================================
__global__ __launch_bounds__(256) void transW_h(
    const float* __restrict__ W, __half* __restrict__ Th, int K, int N)
{
    __shared__ float t[32][33];
    const size_t zoff = (size_t)blockIdx.z * K * N;
    W += zoff; Th += zoff;
    int n0 = blockIdx.x * 32, k0 = blockIdx.y * 32;
    int tx = threadIdx.x & 31, ty = threadIdx.x >> 5;
#pragma unroll
    for (int i = 0; i < 32; i += 8)
        t[ty + i][tx] = W[(size_t)(k0 + ty + i) * N + n0 + tx];
    __syncthreads();
#pragma unroll
    for (int i = 0; i < 32; i += 8)
        Th[(size_t)(n0 + ty + i) * K + k0 + tx] = __float2half_rn(t[tx][ty + i]);
}

// ============================================================
// W2[b][h*64+d][n] = sum_e ctx[bh][d][e] * Wlin[h*64+e][n]
// ============================================================
__global__ __launch_bounds__(256) void w2_kernel(
    const float* __restrict__ ctx, const float* __restrict__ Wlin,
    float* __restrict__ W2)
{
    int bh = blockIdx.x, nb = blockIdx.y;
    int b = bh >> 4, h = bh & 15;
    __shared__ float Cs[64][64];
    __shared__ float Ws[64][64];
    int tid = threadIdx.x;
    for (int i = tid; i < 4096; i += 256)
        ((float*)Cs)[i] = ctx[(size_t)bh * 4096 + i];
    {
        int e = tid >> 2, nq = (tid & 3) << 4;
        const float* src = Wlin + (size_t)(h * 64 + e) * 1024 + nb * 64 + nq;
#pragma unroll
        for (int j = 0; j < 4; j++)
            *(float4*)&Ws[e][nq + j * 4] = *(const float4*)(src + j * 4);
    }
    __syncthreads();
    int tr = tid >> 4, tc = tid & 15;
    float acc[4][4] = {};
#pragma unroll 8
    for (int e = 0; e < 64; e++) {
        float a0 = Cs[tr*4+0][e], a1 = Cs[tr*4+1][e];
        float a2 = Cs[tr*4+2][e], a3 = Cs[tr*4+3][e];
        float4 rb = *(const float4*)&Ws[e][tc * 4];
        acc[0][0]+=a0*rb.x; acc[0][1]+=a0*rb.y; acc[0][2]+=a0*rb.z; acc[0][3]+=a0*rb.w;
        acc[1][0]+=a1*rb.x; acc[1][1]+=a1*rb.y; acc[1][2]+=a1*rb.z; acc[1][3]+=a1*rb.w;
        acc[2][0]+=a2*rb.x; acc[2][1]+=a2*rb.y; acc[2][2]+=a2*rb.z; acc[2][3]+=a2*rb.w;
        acc[3][0]+=a3*rb.x; acc[3][1]+=a3*rb.y; acc[3][2]+=a3*rb.z; acc[3][3]+=a3*rb.w;
    }
#pragma unroll
    for (int i = 0; i < 4; i++) {
        float4 o = make_float4(acc[i][0], acc[i][1], acc[i][2], acc[i][3]);
        *(float4*)(W2 + ((size_t)b * 1024 + h * 64 + tr * 4 + i) * 1024 + nb * 64 + tc * 4) = o;
    }
}

// ============================================================
extern "C" void kernel_launch(void* const* d_in, const int* in_sizes, int n_in,
                              void* d_out, int out_size)
{
    (void)in_sizes; (void)n_in; (void)out_size;
    const float* x    = (const float*)d_in[0];
    const float* Wq   = (const float*)d_in[1];
    const float* Wkv  = (const float*)d_in[2];
    const float* Wlin = (const float*)d_in[3];
    const float* blin = (const float*)d_in[4];
    float* out = (float*)d_out;

    cudaFuncSetAttribute(gemm_mma<0>, cudaFuncAttributeMaxDynamicSharedMemorySize, SMEM_GEMM);
    cudaFuncSetAttribute(gemm_mma<1>, cudaFuncAttributeMaxDynamicSharedMemorySize, SMEM_GEMM);
    cudaFuncSetAttribute(gemm_mma<2>, cudaFuncAttributeMaxDynamicSharedMemorySize, SMEM_GEMM);

    __half *pxh, *pWq, *pWkv, *pYkv, *pQ, *pW2t;
    float *pZ, *pctxp, *pctx, *pW2;
    cudaGetSymbolAddress((void**)&pxh,  g_xh);
    cudaGetSymbolAddress((void**)&pWq,  g_Wqt);
    cudaGetSymbolAddress((void**)&pWkv, g_Wkvt);
    cudaGetSymbolAddress((void**)&pYkv, g_Ykv);
    cudaGetSymbolAddress((void**)&pQ,   g_Q);
    cudaGetSymbolAddress((void**)&pZ,   g_Z);
    cudaGetSymbolAddress((void**)&pctxp,g_ctxp); cudaGetSymbolAddress((void**)&pctx, g_ctx);
    cudaGetSymbolAddress((void**)&pW2,  g_W2);   cudaGetSymbolAddress((void**)&pW2t, g_W2t);

    dim3 blk(256);

    // ---- main stream (0): x convert, KV path, ctx chain ----
    x_to_h<<<(M_*D_/4)/256, blk>>>((const float4*)x, pxh, (size_t)M_*D_/4);
    cudaEventRecord(g_eX, 0);                 // fork point: xh ready

    transW_h<<<dim3(64, 32, 1), blk>>>(Wkv, pWkv, D_, 2*D_);
    zeroZ<<<16, 256>>>(pZ);

    // ---- side stream: Wq prep + Q-proj (independent of KV/ctx) ----
    transW_h<<<dim3(32, 32, 1), blk, 0, g_s2>>>(Wq, pWq, D_, D_);
    cudaStreamWaitEvent(g_s2, g_eX, 0);
    gemm_mma<1><<<dim3(D_/128, M_/128, 1), blk, SMEM_GEMM, g_s2>>>(
        (const uint4*)pxh, (const uint4*)pWq,
        pQ, M_, D_, D_, 0, 0, 0, nullptr, nullptr);
    cudaEventRecord(g_eJ, g_s2);              // join point: Q ready

    // ---- main stream continues: KV-proj then ctx chain ----
    gemm_mma<2><<<dim3(2*D_/128, M_/128, 1), blk, SMEM_GEMM>>>(
        (const uint4*)pxh, (const uint4*)pWkv,
        pYkv, M_, 2*D_, D_, 0, 0, 0, nullptr, pZ);

    ctx_mma<<<dim3(B_*H_, NSPLIT), dim3(128)>>>(pYkv, pctxp);
    ctx_reduce_kernel<<<(B_*H_*64*64)/256, blk>>>(pctxp, pZ, pctx);
    w2_kernel<<<dim3(B_*H_, 16), blk>>>(pctx, Wlin, pW2);
    transW_h<<<dim3(32, 32, B_), blk>>>(pW2, pW2t, D_, D_);

    // ---- join: out-GEMM needs Q (s2) and W2t (main) ----
    cudaStreamWaitEvent(0, g_eJ, 0);
    gemm_mma<0><<<dim3(D_/128, S_/128, B_), blk, SMEM_GEMM>>>(
        (const uint4*)pQ, (const uint4*)pW2t,
        out, S_, D_, D_,
        (size_t)S_*D_/8, (size_t)D_*D_/8, (size_t)S_*D_,
        blin, nullptr);
}

// round 15
// speedup vs baseline: 1.0897x; 1.0099x over previous
#include <cuda_runtime.h>
#include <cuda_fp16.h>
#include <cstdint>

#define B_  4
#define S_  8192
#define D_  1024
#define H_  16
#define M_  (B_*S_)          // 32768
#define SCALE_ 0.125f
#define NSPLIT 16
#define SCHUNK (S_/NSPLIT)   // 512

// ---------------- scratch (device globals) ----------------
__device__ __half g_xh [(size_t)M_*D_];                    // x as fp16
__device__ __half g_Wqt [(size_t)D_*D_];
__device__ __half g_Wkvt[(size_t)2*D_*D_];
__device__ __half g_Ykv[(size_t)M_*2*D_];                  // E=exp(K) | V (fp16)
__device__ __half g_Q  [(size_t)M_*D_];                    // normalized Q (fp16)
__device__ float g_Z [B_*H_*64];
__device__ float g_ctxp[(size_t)B_*H_*NSPLIT*64*64];       // 16.8 MB
__device__ float g_ctx [B_*H_*64*64];
__device__ __half g_W2t[(size_t)B_*D_*D_];

// ---------------- fork/join resources (static init; no device mem) ----
static cudaStream_t g_s2;
static cudaEvent_t  g_eF, g_eX, g_eW, g_eJ;
namespace {
struct _StreamInit {
    _StreamInit() {
        cudaStreamCreateWithFlags(&g_s2, cudaStreamNonBlocking);
        cudaEventCreateWithFlags(&g_eF, cudaEventDisableTiming);
        cudaEventCreateWithFlags(&g_eX, cudaEventDisableTiming);
        cudaEventCreateWithFlags(&g_eW, cudaEventDisableTiming);
        cudaEventCreateWithFlags(&g_eJ, cudaEventDisableTiming);
    }
} _streamInit;
}

// ---------------- helpers ----------------
__device__ __forceinline__ uint32_t smem_u32(const void* p) {
    uint32_t a;
    asm("{ .reg .u64 t; cvta.to.shared.u64 t, %1; cvt.u32.u64 %0, t; }" : "=r"(a) : "l"(p));
    return a;
}
#define SWZ(off) ((off) ^ (((off) >> 3) & 0x70))

__device__ __forceinline__ void cpa16(uint32_t s, const void* g) {
    asm volatile("cp.async.cg.shared.global [%0], [%1], 16;" :: "r"(s), "l"(g));
}
#define CP_COMMIT() asm volatile("cp.async.commit_group;" ::: "memory")
#define CP_WAITG(n) asm volatile("cp.async.wait_group %0;" :: "n"(n) : "memory")

#define LDSM4(r, addr)                                                        \
    asm volatile("ldmatrix.sync.aligned.m8n8.x4.shared.b16 {%0,%1,%2,%3}, [%4];" \
        : "=r"((r)[0]), "=r"((r)[1]), "=r"((r)[2]), "=r"((r)[3]) : "r"(addr))

#define LDSM4T(r, addr)                                                       \
    asm volatile("ldmatrix.sync.aligned.m8n8.x4.trans.shared.b16 {%0,%1,%2,%3}, [%4];" \
        : "=r"((r)[0]), "=r"((r)[1]), "=r"((r)[2]), "=r"((r)[3]) : "r"(addr))

#define MMA16816(c, a, b0, b1)                                                \
    asm volatile("mma.sync.aligned.m16n8k16.row.col.f32.f16.f16.f32 "         \
        "{%0,%1,%2,%3},{%4,%5,%6,%7},{%8,%9},{%0,%1,%2,%3};"                  \
        : "+f"((c)[0]), "+f"((c)[1]), "+f"((c)[2]), "+f"((c)[3])              \
        : "r"((a)[0]), "r"((a)[1]), "r"((a)[2]), "r"((a)[3]),                 \
          "r"(b0), "r"(b1))

static constexpr int STAGE = 32768;           // A16K B16K
static constexpr int SMEM_GEMM = 3 * STAGE;   // 96KB, 3-stage -> 2 CTAs/SM

// EPI modes:
//  0 = fp32 out + bias
//  1 = Q path: exp(acc), in-CTA per-head row softmax-normalize *SCALE, fp16 out
//  2 = KV path: exp(acc) on K-cols (n%128<64), fp16 out, + per-col Z atomics
// ============================================================
// HMMA GEMM: C[M,N] = A[M,K] @ B[N,K]^T  (all fp16 operands)
// CTA 128x128xK64, 8 warps (64x32 each), 3-stage cp.async, SW128.
// ============================================================
template<int EPI>
__global__ __launch_bounds__(256, 2) void gemm_mma(
    const uint4* __restrict__ A, const uint4* __restrict__ Bm,
    void* __restrict__ Cv, int M, int N, int K,
    size_t aBatch, size_t bBatch, size_t cBatch,
    const float* __restrict__ bias, float* __restrict__ Zg)
{
    extern __shared__ __align__(1024) char smem[];
    const uint32_t sbase = smem_u32(smem);
    const int tid = threadIdx.x, wid = tid >> 5, lane = tid & 31;
    const int bn = blockIdx.x * 128, bm = blockIdx.y * 128;
    const int z = blockIdx.z;
    A  += (size_t)z * aBatch;
    Bm += (size_t)z * bBatch;

    const int wm = (wid >> 2) * 64;
    const int wn = (wid & 3) * 32;
    const int Kq = K >> 3;

    const int lr = lane & 7, lq = lane >> 3;
    const uint32_t aRow = lr + (lq & 1) * 8,  aColB = (lq >> 1) * 16;
    const uint32_t bRow = lr + (lq >> 1) * 8, bColB = (lq & 1) * 16;

    float acc[4][4][4] = {};

    auto load_stage = [&](int s, int kq0) {
        uint32_t stb = sbase + s * STAGE;
#pragma unroll
        for (int ii = 0; ii < 4; ii++) {
            int i = tid + ii * 256;
            int r = i >> 3, cc = i & 7;
            uint32_t off = SWZ((uint32_t)(r * 128 + cc * 16));
            cpa16(stb + off,          A  + (size_t)(bm + r) * Kq + kq0 + cc);
            cpa16(stb + 16384 + off,  Bm + (size_t)(bn + r) * Kq + kq0 + cc);
        }
    };

    const int nch = K >> 6;
    load_stage(0, 0);  CP_COMMIT();
    load_stage(1, 8);  CP_COMMIT();

    for (int c = 0; c < nch; ++c) {
        if (c + 1 < nch) { CP_WAITG(1); } else { CP_WAITG(0); }
        __syncthreads();
        if (c + 2 < nch) { load_stage((c + 2) % 3, (c + 2) * 8); CP_COMMIT(); }

        const uint32_t stb = sbase + (c % 3) * STAGE;
#pragma unroll
        for (int t = 0; t < 4; t++) {
            uint32_t a4[4][4], b4[2][4];
#pragma unroll
            for (int mf = 0; mf < 4; mf++) {
                uint32_t off = SWZ((uint32_t)((wm + mf * 16 + aRow) * 128 + t * 32 + aColB));
                LDSM4(a4[mf], stb + off);
            }
#pragma unroll
            for (int p = 0; p < 2; p++) {
                uint32_t off = SWZ((uint32_t)((wn + p * 16 + bRow) * 128 + t * 32 + bColB));
                LDSM4(b4[p], stb + 16384 + off);
            }
#pragma unroll
            for (int mf = 0; mf < 4; mf++)
#pragma unroll
                for (int nf = 0; nf < 4; nf++) {
                    int p = nf >> 1, hh = (nf & 1) * 2;
                    MMA16816(acc[mf][nf], a4[mf], b4[p][hh], b4[p][hh + 1]);
                }
        }
    }

    // ---------------- epilogue ----------------
    const int g = lane >> 2, tt = lane & 3;

    if constexpr (EPI == 0) {
#pragma unroll
        for (int mf = 0; mf < 4; mf++)
#pragma unroll
            for (int nf = 0; nf < 4; nf++) {
                int m = bm + wm + mf * 16 + g;
                int n = bn + wn + nf * 8 + tt * 2;
                float b0 = bias[n], b1 = bias[n + 1];
                float* C = (float*)Cv + (size_t)z * cBatch;
                *(float2*)(C + (size_t)m * N + n) =
                    make_float2(acc[mf][nf][0] + b0, acc[mf][nf][1] + b1);
                *(float2*)(C + (size_t)(m + 8) * N + n) =
                    make_float2(acc[mf][nf][2] + b0, acc[mf][nf][3] + b1);
            }
    }

    if constexpr (EPI == 1) {
#pragma unroll
        for (int mf = 0; mf < 4; mf++)
#pragma unroll
            for (int nf = 0; nf < 4; nf++)
#pragma unroll
                for (int q = 0; q < 4; q++)
                    acc[mf][nf][q] = __expf(acc[mf][nf][q]);
        __syncthreads();                          // stage smem now reusable
        float* sums = (float*)smem;               // [128 rows][2 hcols]
        sums[tid] = 0.f;
        __syncthreads();
        const int hcol = (wn >= 64) ? 1 : 0;
#pragma unroll
        for (int mf = 0; mf < 4; mf++) {
            float sA = 0.f, sB = 0.f;
#pragma unroll
            for (int nf = 0; nf < 4; nf++) {
                sA += acc[mf][nf][0] + acc[mf][nf][1];
                sB += acc[mf][nf][2] + acc[mf][nf][3];
            }
            sA += __shfl_xor_sync(0xffffffffu, sA, 1);
            sA += __shfl_xor_sync(0xffffffffu, sA, 2);
            sB += __shfl_xor_sync(0xffffffffu, sB, 1);
            sB += __shfl_xor_sync(0xffffffffu, sB, 2);
            if (tt == 0) {
                atomicAdd(&sums[(wm + mf * 16 + g) * 2 + hcol], sA);
                atomicAdd(&sums[(wm + mf * 16 + g + 8) * 2 + hcol], sB);
            }
        }
        __syncthreads();
#pragma unroll
        for (int mf = 0; mf < 4; mf++) {
            float invA = SCALE_ / sums[(wm + mf * 16 + g) * 2 + hcol];
            float invB = SCALE_ / sums[(wm + mf * 16 + g + 8) * 2 + hcol];
#pragma unroll
            for (int nf = 0; nf < 4; nf++) {
                int m = bm + wm + mf * 16 + g;
                int n = bn + wn + nf * 8 + tt * 2;
                __half* C = (__half*)Cv;
                *(__half2*)(C + (size_t)m * N + n) =
                    __floats2half2_rn(acc[mf][nf][0] * invA, acc[mf][nf][1] * invA);
                *(__half2*)(C + (size_t)(m + 8) * N + n) =
                    __floats2half2_rn(acc[mf][nf][2] * invB, acc[mf][nf][3] * invB);
            }
        }
    }

    if constexpr (EPI == 2) {
        const bool kcols = (wn < 64);             // n%128<64 -> K half of head
#pragma unroll
        for (int mf = 0; mf < 4; mf++)
#pragma unroll
            for (int nf = 0; nf < 4; nf++) {
                int m = bm + wm + mf * 16 + g;
                int n = bn + wn + nf * 8 + tt * 2;
                float v0 = acc[mf][nf][0], v1 = acc[mf][nf][1];
                float v2 = acc[mf][nf][2], v3 = acc[mf][nf][3];
                if (kcols) {
                    v0 = __expf(v0); v1 = __expf(v1);
                    v2 = __expf(v2); v3 = __expf(v3);
                    acc[mf][nf][0] = v0; acc[mf][nf][1] = v1;
                    acc[mf][nf][2] = v2; acc[mf][nf][3] = v3;
                }
                __half* C = (__half*)Cv;
                *(__half2*)(C + (size_t)m * N + n)       = __floats2half2_rn(v0, v1);
                *(__half2*)(C + (size_t)(m + 8) * N + n) = __floats2half2_rn(v2, v3);
            }
        __syncthreads();
        float* zs = (float*)smem;                 // [64] K-cols of this head
        if (tid < 64) zs[tid] = 0.f;
        __syncthreads();
        if (kcols) {
#pragma unroll
            for (int nf = 0; nf < 4; nf++) {
                float c0 = 0.f, c1 = 0.f;
#pragma unroll
                for (int mf = 0; mf < 4; mf++) {
                    c0 += acc[mf][nf][0] + acc[mf][nf][2];
                    c1 += acc[mf][nf][1] + acc[mf][nf][3];
                }
                int col = wn + nf * 8 + tt * 2;
                atomicAdd(&zs[col], c0);
                atomicAdd(&zs[col + 1], c1);
            }
        }
        __syncthreads();
        if (tid < 64) {
            int b = bm >> 13;
            int h = bn >> 7;
            atomicAdd(&Zg[(b * 16 + h) * 64 + tid], zs[tid]);
        }
    }
}

// ============================================================
// ctx via tensor cores:
// ctxp[bh][sp][d][e] = sum_{s in chunk} E[s,d] * V[s,e]
// ============================================================
static constexpr int CTX_STAGE = 16384;       // E 8KB + V 8KB
__global__ __launch_bounds__(128) void ctx_mma(
    const __half* __restrict__ Ykv, float* __restrict__ ctxp)
{
    __shared__ __align__(1024) char smem[2 * CTX_STAGE];
    const uint32_t sb = smem_u32(smem);
    const int bh = blockIdx.x, sp = blockIdx.y;
    const int b = bh >> 4, h = bh & 15;
    const int tid = threadIdx.x, wid = tid >> 5, lane = tid & 31;
    const __half* base = Ykv + ((size_t)(b * S_) + sp * SCHUNK) * 2048 + h * 128;

    auto load_blk = [&](int st, int s0) {
        uint32_t stb = sb + st * CTX_STAGE;
#pragma unroll
        for (int ii = 0; ii < 8; ii++) {
            int i = tid + ii * 128;
            int r = i >> 4, q = i & 15;
            const __half* g = base + (size_t)(s0 + r) * 2048 + (q & 7) * 8 + (q >> 3) * 64;
            uint32_t off = ((q < 8) ? 0u : 8192u) + SWZ((uint32_t)(r * 128 + (q & 7) * 16));
            cpa16(stb + off, g);
        }
    };

    const int wd = (wid & 1) * 32, we = (wid >> 1) * 32;
    const int lr = lane & 7, lg = lane >> 3;
    float acc[2][4][4] = {};

    load_blk(0, 0); CP_COMMIT();
    for (int blk = 0; blk < SCHUNK / 64; blk++) {
        if (blk + 1 < SCHUNK / 64) {
            load_blk((blk + 1) & 1, (blk + 1) * 64);
            CP_COMMIT(); CP_WAITG(1);
        } else {
            CP_WAITG(0);
        }
        __syncthreads();
        const uint32_t Es = sb + (blk & 1) * CTX_STAGE;
        const uint32_t Vs = Es + 8192;
#pragma unroll
        for (int t = 0; t < 4; t++) {
            uint32_t a4[2][4], b4[2][4];
#pragma unroll
            for (int mi = 0; mi < 2; mi++) {
                uint32_t srow = t * 16 + lr + ((lg >> 1) & 1) * 8;
                uint32_t scolB = (wd + mi * 16) * 2 + (lg & 1) * 16;
                LDSM4T(a4[mi], Es + SWZ(srow * 128 + scolB));
            }
#pragma unroll
            for (int np = 0; np < 2; np++) {
                uint32_t srow = t * 16 + lr + (lg & 1) * 8;
                uint32_t scolB = (we + np * 16) * 2 + (lg >> 1) * 16;
                LDSM4T(b4[np], Vs + SWZ(srow * 128 + scolB));
            }
#pragma unroll
            for (int mi = 0; mi < 2; mi++)
#pragma unroll
                for (int j = 0; j < 4; j++)
                    MMA16816(acc[mi][j], a4[mi], b4[j >> 1][(j & 1) * 2], b4[j >> 1][(j & 1) * 2 + 1]);
        }
        __syncthreads();
    }

    const int g = lane >> 2, tt = lane & 3;
    const size_t po = ((size_t)bh * NSPLIT + sp) * 4096;
#pragma unroll
    for (int mi = 0; mi < 2; mi++)
#pragma unroll
        for (int j = 0; j < 4; j++) {
            int d = wd + mi * 16 + g, e = we + j * 8 + tt * 2;
            *(float2*)(ctxp + po + (size_t)d * 64 + e)       = make_float2(acc[mi][j][0], acc[mi][j][1]);
            *(float2*)(ctxp + po + (size_t)(d + 8) * 64 + e) = make_float2(acc[mi][j][2], acc[mi][j][3]);
        }
}

__global__ __launch_bounds__(256) void ctx_reduce_kernel(
    const float* __restrict__ ctxp, const float* __restrict__ Z,
    float* __restrict__ ctx)
{
    int idx = blockIdx.x * 256 + threadIdx.x;
    int bh = idx >> 12, de = idx & 4095, d = de >> 6;
    float s = 0.f;
#pragma unroll
    for (int i = 0; i < NSPLIT; i++)
        s += ctxp[((size_t)bh * NSPLIT + i) * 4096 + de];
    ctx[idx] = s / Z[bh * 64 + d];
}

// ============================================================
// x fp32 -> fp16 (elementwise); blocks 0-15 also zero Z
// ============================================================
__global__ __launch_bounds__(256) void x_to_h(
    const float4* __restrict__ X, __half* __restrict__ O, size_t n4,
    float* __restrict__ Z)
{
    size_t i = (size_t)blockIdx.x * 256 + threadIdx.x;
    if (blockIdx.x < 16) Z[blockIdx.x * 256 + threadIdx.x] = 0.f;
    if (i >= n4) return;
    float4 v = X[i];
    __half2* p = (__half2*)(O + i * 4);
    p[0] = __floats2half2_rn(v.x, v.y);
    p[1] = __floats2half2_rn(v.z, v.w);
}

// ============================================================
// W[K,N] -> transposed fp16 [N,K]
// ============================================================
__global__ __launch_bounds__(256) void transW_h(
    const float* __restrict__ W, __half* __restrict__ Th, int K, int N)
{
    __shared__ float t[32][33];
    int n0 = blockIdx.x * 32, k0 = blockIdx.y * 32;
    int tx = threadIdx.x & 31, ty = threadIdx.x >> 5;
#pragma unroll
    for (int i = 0; i < 32; i += 8)
        t[ty + i][tx] = W[(size_t)(k0 + ty + i) * N + n0 + tx];
    __syncthreads();
#pragma unroll
    for (int i = 0; i < 32; i += 8)
        Th[(size_t)(n0 + ty + i) * K + k0 + tx] = __float2half_rn(t[tx][ty + i]);
}

// ============================================================
// W2t[b][n][h*64+d] = sum_e ctx[bh][d][e] * Wlin[h*64+e][n]
// (transposed fp16 output written directly from registers)
// ============================================================
__global__ __launch_bounds__(256) void w2_kernel(
    const float* __restrict__ ctx, const float* __restrict__ Wlin,
    __half* __restrict__ W2t)
{
    int bh = blockIdx.x, nb = blockIdx.y;
    int b = bh >> 4, h = bh & 15;
    __shared__ float Cs[64][64];
    __shared__ float Ws[64][64];
    int tid = threadIdx.x;
    for (int i = tid; i < 4096; i += 256)
        ((float*)Cs)[i] = ctx[(size_t)bh * 4096 + i];
    {
        int e = tid >> 2, nq = (tid & 3) << 4;
        const float* src = Wlin + (size_t)(h * 64 + e) * 1024 + nb * 64 + nq;
#pragma unroll
        for (int j = 0; j < 4; j++)
            *(float4*)&Ws[e][nq + j * 4] = *(const float4*)(src + j * 4);
    }
    __syncthreads();
    int tr = tid >> 4, tc = tid & 15;   // tr: d-group, tc: n-group
    float acc[4][4] = {};               // [d][n]
#pragma unroll 8
    for (int e = 0; e < 64; e++) {
        float a0 = Cs[tr*4+0][e], a1 = Cs[tr*4+1][e];
        float a2 = Cs[tr*4+2][e], a3 = Cs[tr*4+3][e];
        float4 rb = *(const float4*)&Ws[e][tc * 4];
        acc[0][0]+=a0*rb.x; acc[0][1]+=a0*rb.y; acc[0][2]+=a0*rb.z; acc[0][3]+=a0*rb.w;
        acc[1][0]+=a1*rb.x; acc[1][1]+=a1*rb.y; acc[1][2]+=a1*rb.z; acc[1][3]+=a1*rb.w;
        acc[2][0]+=a2*rb.x; acc[2][1]+=a2*rb.y; acc[2][2]+=a2*rb.z; acc[2][3]+=a2*rb.w;
        acc[3][0]+=a3*rb.x; acc[3][1]+=a3*rb.y; acc[3][2]+=a3*rb.z; acc[3][3]+=a3*rb.w;
    }
    // write transposed: for each n (j), 4 consecutive k = h*64+tr*4..+3
#pragma unroll
    for (int j = 0; j < 4; j++) {
        int n = nb * 64 + tc * 4 + j;
        __half2 h2a = __floats2half2_rn(acc[0][j], acc[1][j]);
        __half2 h2b = __floats2half2_rn(acc[2][j], acc[3][j]);
        __half2* dst = (__half2*)(W2t + ((size_t)b * 1024 + n) * 1024 + h * 64 + tr * 4);
        dst[0] = h2a; dst[1] = h2b;
    }
}

// ============================================================
extern "C" void kernel_launch(void* const* d_in, const int* in_sizes, int n_in,
                              void* d_out, int out_size)
{
    (void)in_sizes; (void)n_in; (void)out_size;
    const float* x    = (const float*)d_in[0];
    const float* Wq   = (const float*)d_in[1];
    const float* Wkv  = (const float*)d_in[2];
    const float* Wlin = (const float*)d_in[3];
    const float* blin = (const float*)d_in[4];
    float* out = (float*)d_out;

    cudaFuncSetAttribute(gemm_mma<0>, cudaFuncAttributeMaxDynamicSharedMemorySize, SMEM_GEMM);
    cudaFuncSetAttribute(gemm_mma<1>, cudaFuncAttributeMaxDynamicSharedMemorySize, SMEM_GEMM);
    cudaFuncSetAttribute(gemm_mma<2>, cudaFuncAttributeMaxDynamicSharedMemorySize, SMEM_GEMM);

    __half *pxh, *pWq, *pWkv, *pYkv, *pQ, *pW2t;
    float *pZ, *pctxp, *pctx;
    cudaGetSymbolAddress((void**)&pxh,  g_xh);
    cudaGetSymbolAddress((void**)&pWq,  g_Wqt);
    cudaGetSymbolAddress((void**)&pWkv, g_Wkvt);
    cudaGetSymbolAddress((void**)&pYkv, g_Ykv);
    cudaGetSymbolAddress((void**)&pQ,   g_Q);
    cudaGetSymbolAddress((void**)&pZ,   g_Z);
    cudaGetSymbolAddress((void**)&pctxp,g_ctxp); cudaGetSymbolAddress((void**)&pctx, g_ctx);
    cudaGetSymbolAddress((void**)&pW2t, g_W2t);

    dim3 blk(256);

    // ---- fork s2 from the capturing stream FIRST (capture-legal) ----
    cudaEventRecord(g_eF, 0);
    cudaStreamWaitEvent(g_s2, g_eF, 0);

    // ---- s2: weight transposes (x-independent) ----
    transW_h<<<dim3(32, 32, 1), blk, 0, g_s2>>>(Wq, pWq, D_, D_);
    transW_h<<<dim3(64, 32, 1), blk, 0, g_s2>>>(Wkv, pWkv, D_, 2*D_);
    cudaEventRecord(g_eW, g_s2);              // weights ready

    // ---- main: x convert (+ Z zero), concurrent with transW ----
    x_to_h<<<(M_*D_/4)/256, blk>>>((const float4*)x, pxh, (size_t)M_*D_/4, pZ);
    cudaEventRecord(g_eX, 0);                 // xh ready

    // s2: Q-proj after xh ready (Wqt already in s2 order)
    cudaStreamWaitEvent(g_s2, g_eX, 0);
    gemm_mma<1><<<dim3(D_/128, M_/128, 1), blk, SMEM_GEMM, g_s2>>>(
        (const uint4*)pxh, (const uint4*)pWq,
        pQ, M_, D_, D_, 0, 0, 0, nullptr, nullptr);
    cudaEventRecord(g_eJ, g_s2);              // Q ready

    // main: KV-proj after Wkvt ready (xh in-order on main)
    cudaStreamWaitEvent(0, g_eW, 0);
    gemm_mma<2><<<dim3(2*D_/128, M_/128, 1), blk, SMEM_GEMM>>>(
        (const uint4*)pxh, (const uint4*)pWkv,
        pYkv, M_, 2*D_, D_, 0, 0, 0, nullptr, pZ);

    // main: ctx chain (overlaps tail of Q-proj on s2)
    ctx_mma<<<dim3(B_*H_, NSPLIT), dim3(128)>>>(pYkv, pctxp);
    ctx_reduce_kernel<<<(B_*H_*64*64)/256, blk>>>(pctxp, pZ, pctx);
    w2_kernel<<<dim3(B_*H_, 16), blk>>>(pctx, Wlin, pW2t);

    // join: out-GEMM needs Q (s2) and W2t (main)
    cudaStreamWaitEvent(0, g_eJ, 0);
    gemm_mma<0><<<dim3(D_/128, S_/128, B_), blk, SMEM_GEMM>>>(
        (const uint4*)pQ, (const uint4*)pW2t,
        out, S_, D_, D_,
        (size_t)S_*D_/8, (size_t)D_*D_/8, (size_t)S_*D_,
        blin, nullptr);
}